// round 13
// baseline (speedup 1.0000x reference)
#include <cuda_runtime.h>
#include <cuda_bf16.h>
#include <math.h>

#define N_BODY 512
#define NV 6890
#define NVP 6912
#define NJ 24
#define GM 512
#define GN 20736
#define GK 256
#define NVB 108           // NVP / 64

typedef unsigned long long ull;

__device__ __constant__ int d_parents[NJ] =
    {0, 0, 0, 0, 1, 2, 3, 4, 5, 6, 7, 8, 9, 9, 9, 12, 13, 14, 16, 17, 18, 19, 20, 21};

// ---------------- scratch ----------------
__device__ float g_JT[NJ * 3];
__device__ float g_JS[NJ * 30];
__device__ __align__(16) float g_GT[NJ * 12 * N_BODY];      // [j*12+e][n]
__device__ __align__(16) float g_transT[3 * N_BODY];        // [c][n]
__device__ __align__(16) __nv_bfloat16 g_A[GM * GK];        // [n][k]
__device__ __align__(16) __nv_bfloat16 g_B[(size_t)GN * GK];// [c*NVP+v][k]
__device__ __align__(16) float g_jpart[(size_t)NVB * N_BODY * 72];

// ---------------- f32x2 helpers ----------------
__device__ __forceinline__ ull pk2(float a, float b) {
    ull r; asm("mov.b64 %0, {%1, %2};" : "=l"(r) : "f"(a), "f"(b)); return r;
}
__device__ __forceinline__ void upk2(float& a, float& b, ull v) {
    asm("mov.b64 {%0, %1}, %2;" : "=f"(a), "=f"(b) : "l"(v));
}
__device__ __forceinline__ ull fma2_(ull a, ull b, ull c) {
    ull d; asm("fma.rn.f32x2 %0, %1, %2, %3;" : "=l"(d) : "l"(a), "l"(b), "l"(c)); return d;
}

// ---------------- tensor-core helpers ----------------
__device__ __forceinline__ void cp16(unsigned dst, const void* src) {
    asm volatile("cp.async.cg.shared.global [%0], [%1], 16;" :: "r"(dst), "l"(src));
}
__device__ __forceinline__ void ldm4(unsigned* r, unsigned addr) {
    asm volatile("ldmatrix.sync.aligned.m8n8.x4.shared.b16 {%0,%1,%2,%3}, [%4];"
        : "=r"(r[0]), "=r"(r[1]), "=r"(r[2]), "=r"(r[3]) : "r"(addr));
}
__device__ __forceinline__ void mma16816(float* d, const unsigned* a, const unsigned* b) {
    asm volatile("mma.sync.aligned.m16n8k16.row.col.f32.bf16.bf16.f32 "
        "{%0,%1,%2,%3}, {%4,%5,%6,%7}, {%8,%9}, {%0,%1,%2,%3};"
        : "+f"(d[0]), "+f"(d[1]), "+f"(d[2]), "+f"(d[3])
        : "r"(a[0]), "r"(a[1]), "r"(a[2]), "r"(a[3]), "r"(b[0]), "r"(b[1]));
}
__device__ __forceinline__ int swz(int off) { return off ^ ((off >> 3) & 0x70); }

// ---------------- kernel: reduce J_regressor against template/shapedirs ----------------
__global__ void k_pre(const float* __restrict__ Jreg,
                      const float* __restrict__ vt,
                      const float* __restrict__ sd) {
    int j = blockIdx.x;
    int tid = threadIdx.x;
    float acc[33];
#pragma unroll
    for (int i = 0; i < 33; i++) acc[i] = 0.f;
    for (int v = tid; v < NV; v += 256) {
        float r = Jreg[j * NV + v];
#pragma unroll
        for (int c = 0; c < 3; c++) acc[c] += r * vt[v * 3 + c];
#pragma unroll
        for (int i = 0; i < 30; i++) acc[3 + i] += r * sd[v * 30 + i];
    }
#pragma unroll
    for (int i = 0; i < 33; i++) {
#pragma unroll
        for (int off = 16; off > 0; off >>= 1)
            acc[i] += __shfl_down_sync(0xffffffff, acc[i], off);
    }
    __shared__ float red[8][34];
    int wid = tid >> 5, lane = tid & 31;
    if (lane == 0) {
#pragma unroll
        for (int i = 0; i < 33; i++) red[wid][i] = acc[i];
    }
    __syncthreads();
    if (tid < 33) {
        float s = 0.f;
#pragma unroll
        for (int wq = 0; wq < 8; wq++) s += red[wq][tid];
        if (tid < 3) g_JT[j * 3 + tid] = s;
        else         g_JS[j * 30 + (tid - 3)] = s;
    }
}

// ---------------- kernel: build bf16 B [c*NVP+v][k] ----------------
__global__ void __launch_bounds__(256) k_Bbuild(const float* __restrict__ sd,
                                                const float* __restrict__ pd,
                                                const float* __restrict__ vt) {
    int wid = threadIdx.x >> 5, lane = threadIdx.x & 31;
    int row = blockIdx.x * 8 + wid;
    int c = row / NVP, v = row % NVP;
#pragma unroll
    for (int t = 0; t < 8; t++) {
        int k = t * 32 + lane;
        float val = 0.f;
        if (v < NV) {
            if (k < 10)        val = sd[v * 30 + c * 10 + k];
            else if (k < 217)  val = pd[(size_t)v * 621 + c * 207 + (k - 10)];
            else if (k == 217) val = vt[v * 3 + c];
            else if (k == 218) {
                float x = vt[v * 3 + c];
                val = x - __bfloat162float(__float2bfloat16(x));
            }
        }
        g_B[(size_t)row * GK + k] = __float2bfloat16(val);
    }
}

// ---------------- kernel: rodrigues + FK + A row (4 bodies/block) ----------------
__global__ void __launch_bounds__(128) k_body(const float* __restrict__ betas,
                                              const float* __restrict__ thetas,
                                              const float* __restrict__ trans) {
    int wb = threadIdx.x >> 5;
    int lane = threadIdx.x & 31;
    int n = blockIdx.x * 4 + wb;
    __shared__ float sR[4][NJ][9];
    __shared__ float sJ[4][NJ][3];
    __shared__ float sT[4][NJ][3];
    __shared__ float sG[4][NJ][12];

    if (lane < NJ) {
        int j = lane;
        float b[10];
#pragma unroll
        for (int k = 0; k < 10; k++) b[k] = betas[n * 10 + k];
#pragma unroll
        for (int c = 0; c < 3; c++) {
            float a = g_JT[j * 3 + c];
#pragma unroll
            for (int k = 0; k < 10; k++) a += g_JS[j * 30 + c * 10 + k] * b[k];
            sJ[wb][j][c] = a;
        }
        float rx = thetas[n * 72 + j * 3 + 0];
        float ry = thetas[n * 72 + j * 3 + 1];
        float rz = thetas[n * 72 + j * 3 + 2];
        float th = sqrtf(rx * rx + ry * ry + rz * rz) + 1e-8f;
        float inv = 1.0f / th;
        float x = rx * inv, y = ry * inv, z = rz * inv;
        float ct = cosf(th), st = sinf(th), oc = 1.0f - ct;
        sR[wb][j][0] = ct + oc * x * x;      sR[wb][j][1] = oc * x * y - st * z;  sR[wb][j][2] = oc * x * z + st * y;
        sR[wb][j][3] = oc * y * x + st * z;  sR[wb][j][4] = ct + oc * y * y;      sR[wb][j][5] = oc * y * z - st * x;
        sR[wb][j][6] = oc * z * x - st * y;  sR[wb][j][7] = oc * z * y + st * x;  sR[wb][j][8] = ct + oc * z * z;
    }
    __syncwarp();
    if (lane < NJ) {
        int j = lane;
        if (j == 0) {
#pragma unroll
            for (int c = 0; c < 3; c++) sT[wb][0][c] = sJ[wb][0][c];
        } else {
            int p = d_parents[j];
#pragma unroll
            for (int c = 0; c < 3; c++) sT[wb][j][c] = sJ[wb][j][c] - sJ[wb][p][c];
        }
    }
    __syncwarp();
    if (lane == 0) {
#pragma unroll
        for (int r = 0; r < 3; r++) {
            sG[wb][0][r * 4 + 0] = sR[wb][0][r * 3 + 0];
            sG[wb][0][r * 4 + 1] = sR[wb][0][r * 3 + 1];
            sG[wb][0][r * 4 + 2] = sR[wb][0][r * 3 + 2];
            sG[wb][0][r * 4 + 3] = sT[wb][0][r];
        }
        for (int j = 1; j < NJ; j++) {
            int p = d_parents[j];
            float Rn[9], tn[3];
#pragma unroll
            for (int r = 0; r < 3; r++) {
#pragma unroll
                for (int c = 0; c < 3; c++) {
                    Rn[r * 3 + c] = sG[wb][p][r * 4 + 0] * sR[wb][j][0 * 3 + c]
                                  + sG[wb][p][r * 4 + 1] * sR[wb][j][1 * 3 + c]
                                  + sG[wb][p][r * 4 + 2] * sR[wb][j][2 * 3 + c];
                }
                tn[r] = sG[wb][p][r * 4 + 3]
                      + sG[wb][p][r * 4 + 0] * sT[wb][j][0]
                      + sG[wb][p][r * 4 + 1] * sT[wb][j][1]
                      + sG[wb][p][r * 4 + 2] * sT[wb][j][2];
            }
#pragma unroll
            for (int r = 0; r < 3; r++) {
                sG[wb][j][r * 4 + 0] = Rn[r * 3 + 0];
                sG[wb][j][r * 4 + 1] = Rn[r * 3 + 1];
                sG[wb][j][r * 4 + 2] = Rn[r * 3 + 2];
                sG[wb][j][r * 4 + 3] = tn[r];
            }
        }
    }
    __syncwarp();
    if (lane < NJ) {
        int j = lane;
        float t0 = sG[wb][j][3]  - (sG[wb][j][0] * sJ[wb][j][0] + sG[wb][j][1] * sJ[wb][j][1] + sG[wb][j][2]  * sJ[wb][j][2]);
        float t1 = sG[wb][j][7]  - (sG[wb][j][4] * sJ[wb][j][0] + sG[wb][j][5] * sJ[wb][j][1] + sG[wb][j][6]  * sJ[wb][j][2]);
        float t2 = sG[wb][j][11] - (sG[wb][j][8] * sJ[wb][j][0] + sG[wb][j][9] * sJ[wb][j][1] + sG[wb][j][10] * sJ[wb][j][2]);
        sG[wb][j][3] = t0; sG[wb][j][7] = t1; sG[wb][j][11] = t2;
    }
    __syncwarp();
    for (int idx = lane; idx < NJ * 12; idx += 32)
        g_GT[idx * N_BODY + n] = sG[wb][idx / 12][idx % 12];
#pragma unroll
    for (int t = 0; t < 8; t++) {
        int k = t * 32 + lane;
        float val = 0.f;
        if (k < 10) val = betas[n * 10 + k];
        else if (k < 217) {
            int idx = k - 10;
            int j = idx / 9 + 1, e = idx % 9;
            val = sR[wb][j][e];
            if (e == 0 || e == 4 || e == 8) val -= 1.0f;
        }
        else if (k == 217 || k == 218) val = 1.0f;
        g_A[n * GK + k] = __float2bfloat16(val);
    }
    if (lane < 3) g_transT[lane * N_BODY + n] = trans[n * 3 + lane];
}

// ---------------- fused kernel: GEMM + LBS + joint partials ----------------
// block: 64 bodies x 64 verts, 512 threads, 16 warps (4M x 4N), warp tile 16x16 per c
// smem: stages A 2x8KB @0, B 2x24KB @16384 (end 65536); Ct[64][196] overlays [0,50176)
//       w_s [24][128] @65536B; jreg_s [24][64] @77824B; total 83968B
#define CTS 196
#define SMEMB 83968

__global__ void __launch_bounds__(512, 1) k_fused(const float* __restrict__ w,
                                                  const float* __restrict__ jreg,
                                                  float* __restrict__ out) {
    extern __shared__ float sm[];
    unsigned smem = (unsigned)__cvta_generic_to_shared((char*)sm);
    float* Ct     = sm;
    float* w_s    = sm + 16384;   // 65536B / 4
    float* jreg_s = sm + 19456;   // 77824B / 4

    int tid = threadIdx.x, lane = tid & 31, wid = tid >> 5;
    int warp_m = (wid >> 2) * 16, warp_n = (wid & 3) * 16;
    int vbIdx = blockIdx.x;
    int vb = vbIdx * 64;
    int mb = blockIdx.y * 64;

    // stage w (pair-duplicated) + jreg tile (zero-padded)
    for (int i = tid; i < 64 * 24; i += 512) {
        int vl = i / 24, j = i % 24;
        int v = vb + vl;
        float wv = (v < NV) ? w[v * 24 + j] : 0.f;
        w_s[j * 128 + vl * 2]     = wv;
        w_s[j * 128 + vl * 2 + 1] = wv;
        jreg_s[j * 64 + vl] = (v < NV) ? jreg[v * 24 + j] : 0.f;
    }

    float acc[3][2][4];
#pragma unroll
    for (int c = 0; c < 3; c++)
#pragma unroll
        for (int nf = 0; nf < 2; nf++)
#pragma unroll
            for (int q = 0; q < 4; q++) acc[c][nf][q] = 0.f;

#define LDSTG(st, kb)                                                              \
    {                                                                              \
        unsigned sa = smem + (st) * 8192;                                          \
        {                                                                          \
            int r = tid >> 3, u = tid & 7;                                         \
            cp16(sa + swz(r * 128 + u * 16),                                       \
                 (const char*)g_A + (size_t)(mb + r) * 512 + (kb) * 128 + u * 16); \
        }                                                                          \
        _Pragma("unroll")                                                          \
        for (int t = 0; t < 3; t++) {                                              \
            int i = tid + t * 512; int c = i >> 9, rr = (i >> 3) & 63, u = i & 7;  \
            unsigned sb = smem + 16384 + (st) * 24576 + c * 8192;                  \
            cp16(sb + swz(rr * 128 + u * 16),                                      \
                 (const char*)g_B + (size_t)(c * NVP + vb + rr) * 512 + (kb) * 128 + u * 16); \
        }                                                                          \
        asm volatile("cp.async.commit_group;");                                    \
    }

    LDSTG(0, 0);
#pragma unroll
    for (int kb = 0; kb < 4; kb++) {
        if (kb < 3) LDSTG((kb + 1) & 1, kb + 1);
        if (kb < 3) asm volatile("cp.async.wait_group 1;");
        else        asm volatile("cp.async.wait_group 0;");
        __syncthreads();
        unsigned sa = smem + (kb & 1) * 8192;
#pragma unroll
        for (int s = 0; s < 4; s++) {
            unsigned af[4];
            {
                int row = warp_m + (lane & 7) + ((lane >> 3) & 1) * 8;
                ldm4(af, sa + swz(row * 128 + s * 32 + ((lane >> 4) & 1) * 16));
            }
#pragma unroll
            for (int c = 0; c < 3; c++) {
                unsigned sb = smem + 16384 + (kb & 1) * 24576 + c * 8192;
                unsigned r[4];
                int row = warp_n + (lane & 7) + ((lane >> 4) & 1) * 8;
                ldm4(r, sb + swz(row * 128 + s * 32 + ((lane >> 3) & 1) * 16));
                mma16816(acc[c][0], af, r);
                mma16816(acc[c][1], af, r + 2);
            }
        }
        __syncthreads();
    }
#undef LDSTG

    // ---- epilogue: acc -> Ct (v_posed; vt folded via hi/lo columns) ----
#pragma unroll
    for (int c = 0; c < 3; c++)
#pragma unroll
        for (int nf = 0; nf < 2; nf++) {
            int r0 = warp_m + (lane >> 2);
            int L = warp_n + nf * 8 + (lane & 3) * 2;
            Ct[r0 * CTS + L * 3 + c]             = acc[c][nf][0];
            Ct[r0 * CTS + (L + 1) * 3 + c]       = acc[c][nf][1];
            Ct[(r0 + 8) * CTS + L * 3 + c]       = acc[c][nf][2];
            Ct[(r0 + 8) * CTS + (L + 1) * 3 + c] = acc[c][nf][3];
        }
    __syncthreads();

    // ---- skinning in place: thread = body-pair (32) x vert-quad (16) ----
    {
        int bp = tid >> 4, vq = tid & 15;
        int n0 = bp * 2;
        ull B[4][3], o[4][3];
#pragma unroll
        for (int vv = 0; vv < 4; vv++)
#pragma unroll
            for (int c = 0; c < 3; c++)
                B[vv][c] = pk2(Ct[n0 * CTS + (vq * 4 + vv) * 3 + c],
                               Ct[(n0 + 1) * CTS + (vq * 4 + vv) * 3 + c]);
#pragma unroll
        for (int c = 0; c < 3; c++) {
            ull t2 = *(const ull*)(g_transT + c * N_BODY + mb + n0);
#pragma unroll
            for (int vv = 0; vv < 4; vv++) o[vv][c] = t2;
        }
#pragma unroll 1
        for (int j = 0; j < NJ; j++) {
            ull g2[12];
#pragma unroll
            for (int e = 0; e < 12; e++)
                g2[e] = *(const ull*)(g_GT + (j * 12 + e) * N_BODY + mb + n0);
#pragma unroll
            for (int vv = 0; vv < 4; vv++) {
                ull w2 = *(const ull*)(w_s + j * 128 + (vq * 4 + vv) * 2);
                ull tx = fma2_(g2[0], B[vv][0], fma2_(g2[1], B[vv][1], fma2_(g2[2],  B[vv][2], g2[3])));
                ull ty = fma2_(g2[4], B[vv][0], fma2_(g2[5], B[vv][1], fma2_(g2[6],  B[vv][2], g2[7])));
                ull tz = fma2_(g2[8], B[vv][0], fma2_(g2[9], B[vv][1], fma2_(g2[10], B[vv][2], g2[11])));
                o[vv][0] = fma2_(w2, tx, o[vv][0]);
                o[vv][1] = fma2_(w2, ty, o[vv][1]);
                o[vv][2] = fma2_(w2, tz, o[vv][2]);
            }
        }
        __syncthreads();
#pragma unroll
        for (int vv = 0; vv < 4; vv++)
#pragma unroll
            for (int c = 0; c < 3; c++) {
                float x0, x1;
                upk2(x0, x1, o[vv][c]);
                Ct[n0 * CTS + (vq * 4 + vv) * 3 + c]       = x0;
                Ct[(n0 + 1) * CTS + (vq * 4 + vv) * 3 + c] = x1;
            }
    }
    __syncthreads();

    // ---- stream out (float2 coalesced) ----
    int nvleft = NV - vb; if (nvleft > 64) nvleft = 64;
    int flim2 = nvleft * 3 / 2;
    for (int i = tid; i < 64 * 96; i += 512) {
        int nl = i / 96, q = i % 96;
        if (q < flim2)
            *(float2*)(out + (size_t)(mb + nl) * (NV * 3) + (size_t)vb * 3 + 2 * q) =
                *(const float2*)(Ct + nl * CTS + 2 * q);
    }

    // ---- joint partials: thread = body (64) x joint-triple (8) ----
    {
        int nl = tid >> 3, jq = tid & 7;
        float ja[9];
#pragma unroll
        for (int q = 0; q < 9; q++) ja[q] = 0.f;
#pragma unroll 4
        for (int v = 0; v < 64; v++) {
            float r0 = Ct[nl * CTS + v * 3 + 0];
            float r1 = Ct[nl * CTS + v * 3 + 1];
            float r2 = Ct[nl * CTS + v * 3 + 2];
#pragma unroll
            for (int j = 0; j < 3; j++) {
                float jr = jreg_s[(jq * 3 + j) * 64 + v];
                ja[j * 3 + 0] += jr * r0;
                ja[j * 3 + 1] += jr * r1;
                ja[j * 3 + 2] += jr * r2;
            }
        }
        float* dst = g_jpart + (size_t)vbIdx * (N_BODY * 72) + (mb + nl) * 72 + jq * 9;
#pragma unroll
        for (int q = 0; q < 9; q++) dst[q] = ja[q];
    }
}

// ---------------- kernel: reduce joint partials ----------------
__global__ void __launch_bounds__(256) k_jred(float* __restrict__ jout) {
    int i = blockIdx.x * 256 + threadIdx.x;
    if (i < N_BODY * 72) {
        float s = 0.f;
        for (int b = 0; b < NVB; b++) s += g_jpart[(size_t)b * (N_BODY * 72) + i];
        jout[i] = s;
    }
}

// ---------------- launch ----------------
extern "C" void kernel_launch(void* const* d_in, const int* in_sizes, int n_in,
                              void* d_out, int out_size) {
    const float* betas  = (const float*)d_in[0];
    const float* thetas = (const float*)d_in[1];
    const float* trans  = (const float*)d_in[2];
    const float* vt     = (const float*)d_in[3];
    const float* sd     = (const float*)d_in[4];
    const float* pd     = (const float*)d_in[5];
    const float* Jreg   = (const float*)d_in[6];
    const float* jreg   = (const float*)d_in[7];
    const float* w      = (const float*)d_in[8];
    float* out  = (float*)d_out;
    float* jout = out + (size_t)N_BODY * NV * 3;

    k_pre<<<NJ, 256>>>(Jreg, vt, sd);
    k_Bbuild<<<GN / 8, 256>>>(sd, pd, vt);
    k_body<<<N_BODY / 4, 128>>>(betas, thetas, trans);

    cudaFuncSetAttribute(k_fused, cudaFuncAttributeMaxDynamicSharedMemorySize, SMEMB);
    dim3 fgrid(NVB, N_BODY / 64);
    k_fused<<<fgrid, 512, SMEMB>>>(w, jreg, out);

    k_jred<<<(N_BODY * 72 + 255) / 256, 256>>>(jout);
}

// round 14
// speedup vs baseline: 1.4309x; 1.4309x over previous
#include <cuda_runtime.h>
#include <cuda_bf16.h>
#include <math.h>

#define N_BODY 512
#define NV 6890
#define NVP 6912
#define NJ 24
#define GM 512
#define GN 20736
#define GK 256
#define NVB 108           // NVP / 64

typedef unsigned long long ull;

__device__ __constant__ int d_parents[NJ] =
    {0, 0, 0, 0, 1, 2, 3, 4, 5, 6, 7, 8, 9, 9, 9, 12, 13, 14, 16, 17, 18, 19, 20, 21};

// ---------------- scratch ----------------
__device__ float g_JT[NJ * 3];
__device__ float g_JS[NJ * 30];
__device__ __align__(16) float g_GT[NJ * 12 * N_BODY];      // [j*12+e][n]
__device__ __align__(16) float g_transT[3 * N_BODY];        // [c][n]
__device__ __align__(16) __nv_bfloat16 g_A[GM * GK];        // [n][k]
__device__ __align__(16) __nv_bfloat16 g_B[(size_t)GN * GK];// [c*NVP+v][k]
__device__ __align__(16) float g_jpart[(size_t)NVB * N_BODY * 72];

// ---------------- f32x2 helpers ----------------
__device__ __forceinline__ ull pk2(float a, float b) {
    ull r; asm("mov.b64 %0, {%1, %2};" : "=l"(r) : "f"(a), "f"(b)); return r;
}
__device__ __forceinline__ void upk2(float& a, float& b, ull v) {
    asm("mov.b64 {%0, %1}, %2;" : "=f"(a), "=f"(b) : "l"(v));
}
__device__ __forceinline__ ull fma2_(ull a, ull b, ull c) {
    ull d; asm("fma.rn.f32x2 %0, %1, %2, %3;" : "=l"(d) : "l"(a), "l"(b), "l"(c)); return d;
}

// ---------------- tensor-core helpers ----------------
__device__ __forceinline__ void cp16(unsigned dst, const void* src) {
    asm volatile("cp.async.cg.shared.global [%0], [%1], 16;" :: "r"(dst), "l"(src));
}
__device__ __forceinline__ void ldm4(unsigned* r, unsigned addr) {
    asm volatile("ldmatrix.sync.aligned.m8n8.x4.shared.b16 {%0,%1,%2,%3}, [%4];"
        : "=r"(r[0]), "=r"(r[1]), "=r"(r[2]), "=r"(r[3]) : "r"(addr));
}
__device__ __forceinline__ void mma16816(float* d, const unsigned* a, const unsigned* b) {
    asm volatile("mma.sync.aligned.m16n8k16.row.col.f32.bf16.bf16.f32 "
        "{%0,%1,%2,%3}, {%4,%5,%6,%7}, {%8,%9}, {%0,%1,%2,%3};"
        : "+f"(d[0]), "+f"(d[1]), "+f"(d[2]), "+f"(d[3])
        : "r"(a[0]), "r"(a[1]), "r"(a[2]), "r"(a[3]), "r"(b[0]), "r"(b[1]));
}
__device__ __forceinline__ int swz(int off) { return off ^ ((off >> 3) & 0x70); }

// ---------------- kernel: reduce J_regressor against template/shapedirs ----------------
__global__ void k_pre(const float* __restrict__ Jreg,
                      const float* __restrict__ vt,
                      const float* __restrict__ sd) {
    int j = blockIdx.x;
    int tid = threadIdx.x;
    float acc[33];
#pragma unroll
    for (int i = 0; i < 33; i++) acc[i] = 0.f;
    for (int v = tid; v < NV; v += 256) {
        float r = Jreg[j * NV + v];
#pragma unroll
        for (int c = 0; c < 3; c++) acc[c] += r * vt[v * 3 + c];
#pragma unroll
        for (int i = 0; i < 30; i++) acc[3 + i] += r * sd[v * 30 + i];
    }
#pragma unroll
    for (int i = 0; i < 33; i++) {
#pragma unroll
        for (int off = 16; off > 0; off >>= 1)
            acc[i] += __shfl_down_sync(0xffffffff, acc[i], off);
    }
    __shared__ float red[8][34];
    int wid = tid >> 5, lane = tid & 31;
    if (lane == 0) {
#pragma unroll
        for (int i = 0; i < 33; i++) red[wid][i] = acc[i];
    }
    __syncthreads();
    if (tid < 33) {
        float s = 0.f;
#pragma unroll
        for (int wq = 0; wq < 8; wq++) s += red[wq][tid];
        if (tid < 3) g_JT[j * 3 + tid] = s;
        else         g_JS[j * 30 + (tid - 3)] = s;
    }
}

// ---------------- kernel: build bf16 B [c*NVP+v][k] ----------------
__global__ void __launch_bounds__(256) k_Bbuild(const float* __restrict__ sd,
                                                const float* __restrict__ pd,
                                                const float* __restrict__ vt) {
    int wid = threadIdx.x >> 5, lane = threadIdx.x & 31;
    int row = blockIdx.x * 8 + wid;
    int c = row / NVP, v = row % NVP;
#pragma unroll
    for (int t = 0; t < 8; t++) {
        int k = t * 32 + lane;
        float val = 0.f;
        if (v < NV) {
            if (k < 10)        val = sd[v * 30 + c * 10 + k];
            else if (k < 217)  val = pd[(size_t)v * 621 + c * 207 + (k - 10)];
            else if (k == 217) val = vt[v * 3 + c];
            else if (k == 218) {
                float x = vt[v * 3 + c];
                val = x - __bfloat162float(__float2bfloat16(x));
            }
        }
        g_B[(size_t)row * GK + k] = __float2bfloat16(val);
    }
}

// ---------------- kernel: rodrigues + FK + A row (4 bodies/block) ----------------
__global__ void __launch_bounds__(128) k_body(const float* __restrict__ betas,
                                              const float* __restrict__ thetas,
                                              const float* __restrict__ trans) {
    int wb = threadIdx.x >> 5;
    int lane = threadIdx.x & 31;
    int n = blockIdx.x * 4 + wb;
    __shared__ float sR[4][NJ][9];
    __shared__ float sJ[4][NJ][3];
    __shared__ float sT[4][NJ][3];
    __shared__ float sG[4][NJ][12];

    if (lane < NJ) {
        int j = lane;
        float b[10];
#pragma unroll
        for (int k = 0; k < 10; k++) b[k] = betas[n * 10 + k];
#pragma unroll
        for (int c = 0; c < 3; c++) {
            float a = g_JT[j * 3 + c];
#pragma unroll
            for (int k = 0; k < 10; k++) a += g_JS[j * 30 + c * 10 + k] * b[k];
            sJ[wb][j][c] = a;
        }
        float rx = thetas[n * 72 + j * 3 + 0];
        float ry = thetas[n * 72 + j * 3 + 1];
        float rz = thetas[n * 72 + j * 3 + 2];
        float th = sqrtf(rx * rx + ry * ry + rz * rz) + 1e-8f;
        float inv = 1.0f / th;
        float x = rx * inv, y = ry * inv, z = rz * inv;
        float ct = cosf(th), st = sinf(th), oc = 1.0f - ct;
        sR[wb][j][0] = ct + oc * x * x;      sR[wb][j][1] = oc * x * y - st * z;  sR[wb][j][2] = oc * x * z + st * y;
        sR[wb][j][3] = oc * y * x + st * z;  sR[wb][j][4] = ct + oc * y * y;      sR[wb][j][5] = oc * y * z - st * x;
        sR[wb][j][6] = oc * z * x - st * y;  sR[wb][j][7] = oc * z * y + st * x;  sR[wb][j][8] = ct + oc * z * z;
    }
    __syncwarp();
    if (lane < NJ) {
        int j = lane;
        if (j == 0) {
#pragma unroll
            for (int c = 0; c < 3; c++) sT[wb][0][c] = sJ[wb][0][c];
        } else {
            int p = d_parents[j];
#pragma unroll
            for (int c = 0; c < 3; c++) sT[wb][j][c] = sJ[wb][j][c] - sJ[wb][p][c];
        }
    }
    __syncwarp();
    if (lane == 0) {
#pragma unroll
        for (int r = 0; r < 3; r++) {
            sG[wb][0][r * 4 + 0] = sR[wb][0][r * 3 + 0];
            sG[wb][0][r * 4 + 1] = sR[wb][0][r * 3 + 1];
            sG[wb][0][r * 4 + 2] = sR[wb][0][r * 3 + 2];
            sG[wb][0][r * 4 + 3] = sT[wb][0][r];
        }
        for (int j = 1; j < NJ; j++) {
            int p = d_parents[j];
            float Rn[9], tn[3];
#pragma unroll
            for (int r = 0; r < 3; r++) {
#pragma unroll
                for (int c = 0; c < 3; c++) {
                    Rn[r * 3 + c] = sG[wb][p][r * 4 + 0] * sR[wb][j][0 * 3 + c]
                                  + sG[wb][p][r * 4 + 1] * sR[wb][j][1 * 3 + c]
                                  + sG[wb][p][r * 4 + 2] * sR[wb][j][2 * 3 + c];
                }
                tn[r] = sG[wb][p][r * 4 + 3]
                      + sG[wb][p][r * 4 + 0] * sT[wb][j][0]
                      + sG[wb][p][r * 4 + 1] * sT[wb][j][1]
                      + sG[wb][p][r * 4 + 2] * sT[wb][j][2];
            }
#pragma unroll
            for (int r = 0; r < 3; r++) {
                sG[wb][j][r * 4 + 0] = Rn[r * 3 + 0];
                sG[wb][j][r * 4 + 1] = Rn[r * 3 + 1];
                sG[wb][j][r * 4 + 2] = Rn[r * 3 + 2];
                sG[wb][j][r * 4 + 3] = tn[r];
            }
        }
    }
    __syncwarp();
    if (lane < NJ) {
        int j = lane;
        float t0 = sG[wb][j][3]  - (sG[wb][j][0] * sJ[wb][j][0] + sG[wb][j][1] * sJ[wb][j][1] + sG[wb][j][2]  * sJ[wb][j][2]);
        float t1 = sG[wb][j][7]  - (sG[wb][j][4] * sJ[wb][j][0] + sG[wb][j][5] * sJ[wb][j][1] + sG[wb][j][6]  * sJ[wb][j][2]);
        float t2 = sG[wb][j][11] - (sG[wb][j][8] * sJ[wb][j][0] + sG[wb][j][9] * sJ[wb][j][1] + sG[wb][j][10] * sJ[wb][j][2]);
        sG[wb][j][3] = t0; sG[wb][j][7] = t1; sG[wb][j][11] = t2;
    }
    __syncwarp();
    for (int idx = lane; idx < NJ * 12; idx += 32)
        g_GT[idx * N_BODY + n] = sG[wb][idx / 12][idx % 12];
#pragma unroll
    for (int t = 0; t < 8; t++) {
        int k = t * 32 + lane;
        float val = 0.f;
        if (k < 10) val = betas[n * 10 + k];
        else if (k < 217) {
            int idx = k - 10;
            int j = idx / 9 + 1, e = idx % 9;
            val = sR[wb][j][e];
            if (e == 0 || e == 4 || e == 8) val -= 1.0f;
        }
        else if (k == 217 || k == 218) val = 1.0f;
        g_A[n * GK + k] = __float2bfloat16(val);
    }
    if (lane < 3) g_transT[lane * N_BODY + n] = trans[n * 3 + lane];
}

// ---------------- fused kernel: GEMM + LBS + joint partials ----------------
// block: 64 bodies x 64 verts, 256 threads, 8 warps (2M x 4N), warp tile 32x16 per c
// smem (floats):
//   stages: A 2x8KB @0B, B 2x24KB @16384B  -> [0, 16384) floats, GEMM phase only
//   Ct[64][196]  @0        (12544 fl)  — overlays stages after mainloop
//   jreg_s[24][65] @12544  (1560 fl)   — loaded after mainloop
//   w_s[24][128]  @14104   (3072 fl)   — loaded after mainloop (pair-duplicated)
//   sG[288][32]   @17176   (9216 fl)   — per 32-body half
// total 26392 floats = 105568 B  -> 2 blocks/SM
#define CTS 196
#define JREG_F 12544
#define W_F    14104
#define SG_F   17176
#define SMEMB  105568

__global__ void __launch_bounds__(256, 2) k_fused(const float* __restrict__ w,
                                                  const float* __restrict__ jreg,
                                                  float* __restrict__ out) {
    extern __shared__ float sm[];
    unsigned smem = (unsigned)__cvta_generic_to_shared((char*)sm);
    float* Ct     = sm;
    float* jreg_s = sm + JREG_F;
    float* w_s    = sm + W_F;
    float* sG     = sm + SG_F;

    int tid = threadIdx.x, lane = tid & 31, wid = tid >> 5;
    int warp_m = (wid >> 2) * 32, warp_n = (wid & 3) * 16;
    int vbIdx = blockIdx.x;
    int vb = vbIdx * 64;
    int mb = blockIdx.y * 64;

    float acc[3][2][2][4];
#pragma unroll
    for (int c = 0; c < 3; c++)
#pragma unroll
        for (int mf = 0; mf < 2; mf++)
#pragma unroll
            for (int nf = 0; nf < 2; nf++)
#pragma unroll
                for (int q = 0; q < 4; q++) acc[c][mf][nf][q] = 0.f;

#define LDSTG(st, kb)                                                              \
    {                                                                              \
        unsigned sa = smem + (st) * 8192;                                          \
        _Pragma("unroll")                                                          \
        for (int t = 0; t < 2; t++) {                                              \
            int i = tid + t * 256; int r = i >> 3, u = i & 7;                      \
            cp16(sa + swz(r * 128 + u * 16),                                       \
                 (const char*)g_A + (size_t)(mb + r) * 512 + (kb) * 128 + u * 16); \
        }                                                                          \
        _Pragma("unroll")                                                          \
        for (int t = 0; t < 6; t++) {                                              \
            int i = tid + t * 256; int c = i >> 9, rr = (i >> 3) & 63, u = i & 7;  \
            unsigned sb = smem + 16384 + (st) * 24576 + c * 8192;                  \
            cp16(sb + swz(rr * 128 + u * 16),                                      \
                 (const char*)g_B + (size_t)(c * NVP + vb + rr) * 512 + (kb) * 128 + u * 16); \
        }                                                                          \
        asm volatile("cp.async.commit_group;");                                    \
    }

    LDSTG(0, 0);
#pragma unroll
    for (int kb = 0; kb < 4; kb++) {
        if (kb < 3) LDSTG((kb + 1) & 1, kb + 1);
        if (kb < 3) asm volatile("cp.async.wait_group 1;");
        else        asm volatile("cp.async.wait_group 0;");
        __syncthreads();
        unsigned sa = smem + (kb & 1) * 8192;
#pragma unroll
        for (int s = 0; s < 4; s++) {
            unsigned af[2][4];
#pragma unroll
            for (int mf = 0; mf < 2; mf++) {
                int row = warp_m + mf * 16 + (lane & 7) + ((lane >> 3) & 1) * 8;
                ldm4(af[mf], sa + swz(row * 128 + s * 32 + ((lane >> 4) & 1) * 16));
            }
#pragma unroll
            for (int c = 0; c < 3; c++) {
                unsigned sb = smem + 16384 + (kb & 1) * 24576 + c * 8192;
                unsigned r[4];
                int row = warp_n + (lane & 7) + ((lane >> 4) & 1) * 8;
                ldm4(r, sb + swz(row * 128 + s * 32 + ((lane >> 3) & 1) * 16));
#pragma unroll
                for (int mf = 0; mf < 2; mf++) {
                    mma16816(acc[c][mf][0], af[mf], r);
                    mma16816(acc[c][mf][1], af[mf], r + 2);
                }
            }
        }
        __syncthreads();
    }
#undef LDSTG

    // ---- epilogue: acc -> Ct (v_posed; vt folded via hi/lo columns) ----
#pragma unroll
    for (int c = 0; c < 3; c++)
#pragma unroll
        for (int mf = 0; mf < 2; mf++)
#pragma unroll
            for (int nf = 0; nf < 2; nf++) {
                int r0 = warp_m + mf * 16 + (lane >> 2);
                int L = warp_n + nf * 8 + (lane & 3) * 2;
                Ct[r0 * CTS + L * 3 + c]             = acc[c][mf][nf][0];
                Ct[r0 * CTS + (L + 1) * 3 + c]       = acc[c][mf][nf][1];
                Ct[(r0 + 8) * CTS + L * 3 + c]       = acc[c][mf][nf][2];
                Ct[(r0 + 8) * CTS + (L + 1) * 3 + c] = acc[c][mf][nf][3];
            }

    // ---- load w (pair-duplicated), jreg (row-padded to 65) ----
    for (int i = tid; i < 64 * 24; i += 256) {
        int vl = i / 24, j = i % 24;
        int v = vb + vl;
        float wv = (v < NV) ? w[v * 24 + j] : 0.f;
        w_s[j * 128 + vl * 2]     = wv;
        w_s[j * 128 + vl * 2 + 1] = wv;
        jreg_s[j * 65 + vl] = (v < NV) ? jreg[v * 24 + j] : 0.f;
    }

    // ---- skinning in place, two 32-body halves; thread = body-pair(16) x vert-quad(16) ----
    int bp = tid >> 4, vq = tid & 15;
#pragma unroll 1
    for (int h = 0; h < 2; h++) {
        __syncthreads();   // epilogue/w/jreg stores done (h=0); prior-half sG reads done (h=1)
        for (int i = tid; i < 288 * 32; i += 256)
            sG[i] = g_GT[(i >> 5) * N_BODY + mb + h * 32 + (i & 31)];
        __syncthreads();

        int n0 = h * 32 + bp * 2;
        ull B[4][3], o[4][3];
#pragma unroll
        for (int vv = 0; vv < 4; vv++)
#pragma unroll
            for (int c = 0; c < 3; c++)
                B[vv][c] = pk2(Ct[n0 * CTS + (vq * 4 + vv) * 3 + c],
                               Ct[(n0 + 1) * CTS + (vq * 4 + vv) * 3 + c]);
#pragma unroll
        for (int c = 0; c < 3; c++) {
            ull t2 = *(const ull*)(g_transT + c * N_BODY + mb + n0);
#pragma unroll
            for (int vv = 0; vv < 4; vv++) o[vv][c] = t2;
        }
#pragma unroll 1
        for (int j = 0; j < NJ; j++) {
            ull g2[12];
#pragma unroll
            for (int e = 0; e < 12; e++)
                g2[e] = *(const ull*)(sG + (j * 12 + e) * 32 + bp * 2);
#pragma unroll
            for (int vv = 0; vv < 4; vv++) {
                ull w2 = *(const ull*)(w_s + j * 128 + (vq * 4 + vv) * 2);
                ull tx = fma2_(g2[0], B[vv][0], fma2_(g2[1], B[vv][1], fma2_(g2[2],  B[vv][2], g2[3])));
                ull ty = fma2_(g2[4], B[vv][0], fma2_(g2[5], B[vv][1], fma2_(g2[6],  B[vv][2], g2[7])));
                ull tz = fma2_(g2[8], B[vv][0], fma2_(g2[9], B[vv][1], fma2_(g2[10], B[vv][2], g2[11])));
                o[vv][0] = fma2_(w2, tx, o[vv][0]);
                o[vv][1] = fma2_(w2, ty, o[vv][1]);
                o[vv][2] = fma2_(w2, tz, o[vv][2]);
            }
        }
        // write back: each thread owns rows n0,n0+1 / cols vq*4..+3 — no hazard
#pragma unroll
        for (int vv = 0; vv < 4; vv++)
#pragma unroll
            for (int c = 0; c < 3; c++) {
                float x0, x1;
                upk2(x0, x1, o[vv][c]);
                Ct[n0 * CTS + (vq * 4 + vv) * 3 + c]       = x0;
                Ct[(n0 + 1) * CTS + (vq * 4 + vv) * 3 + c] = x1;
            }
    }
    __syncthreads();

    // ---- stream out (float2 coalesced) ----
    int nvleft = NV - vb; if (nvleft > 64) nvleft = 64;
    int flim2 = nvleft * 3 / 2;
    for (int i = tid; i < 64 * 96; i += 256) {
        int nl = i / 96, q = i % 96;
        if (q < flim2)
            *(float2*)(out + (size_t)(mb + nl) * (NV * 3) + (size_t)vb * 3 + 2 * q) =
                *(const float2*)(Ct + nl * CTS + 2 * q);
    }

    // ---- joint partials: thread = body (64) x joint-sextet (4) ----
    {
        int nl = tid >> 2, jq = tid & 3;
        float ja[18];
#pragma unroll
        for (int q = 0; q < 18; q++) ja[q] = 0.f;
#pragma unroll 4
        for (int v = 0; v < 64; v++) {
            float r0 = Ct[nl * CTS + v * 3 + 0];
            float r1 = Ct[nl * CTS + v * 3 + 1];
            float r2 = Ct[nl * CTS + v * 3 + 2];
#pragma unroll
            for (int j = 0; j < 6; j++) {
                float jr = jreg_s[(jq * 6 + j) * 65 + v];
                ja[j * 3 + 0] += jr * r0;
                ja[j * 3 + 1] += jr * r1;
                ja[j * 3 + 2] += jr * r2;
            }
        }
        float* dst = g_jpart + (size_t)vbIdx * (N_BODY * 72) + (mb + nl) * 72 + jq * 18;
#pragma unroll
        for (int q = 0; q < 18; q++) dst[q] = ja[q];
    }
}

// ---------------- kernel: reduce joint partials ----------------
__global__ void __launch_bounds__(256) k_jred(float* __restrict__ jout) {
    int i = blockIdx.x * 256 + threadIdx.x;
    if (i < N_BODY * 72) {
        float s = 0.f;
        for (int b = 0; b < NVB; b++) s += g_jpart[(size_t)b * (N_BODY * 72) + i];
        jout[i] = s;
    }
}

// ---------------- launch ----------------
extern "C" void kernel_launch(void* const* d_in, const int* in_sizes, int n_in,
                              void* d_out, int out_size) {
    const float* betas  = (const float*)d_in[0];
    const float* thetas = (const float*)d_in[1];
    const float* trans  = (const float*)d_in[2];
    const float* vt     = (const float*)d_in[3];
    const float* sd     = (const float*)d_in[4];
    const float* pd     = (const float*)d_in[5];
    const float* Jreg   = (const float*)d_in[6];
    const float* jreg   = (const float*)d_in[7];
    const float* w      = (const float*)d_in[8];
    float* out  = (float*)d_out;
    float* jout = out + (size_t)N_BODY * NV * 3;

    k_pre<<<NJ, 256>>>(Jreg, vt, sd);
    k_Bbuild<<<GN / 8, 256>>>(sd, pd, vt);
    k_body<<<N_BODY / 4, 128>>>(betas, thetas, trans);

    cudaFuncSetAttribute(k_fused, cudaFuncAttributeMaxDynamicSharedMemorySize, SMEMB);
    dim3 fgrid(NVB, N_BODY / 64);
    k_fused<<<fgrid, 256, SMEMB>>>(w, jreg, out);

    k_jred<<<(N_BODY * 72 + 255) / 256, 256>>>(jout);
}

// round 16
// speedup vs baseline: 1.4817x; 1.0355x over previous
#include <cuda_runtime.h>
#include <cuda_bf16.h>
#include <math.h>

#define N_BODY 512
#define NV 6890
#define NVP 6912
#define NJ 24
#define GM 512
#define GN 20736
#define GK 256
#define NVB 108           // NVP / 64

typedef unsigned long long ull;

__device__ __constant__ int d_parents[NJ] =
    {0, 0, 0, 0, 1, 2, 3, 4, 5, 6, 7, 8, 9, 9, 9, 12, 13, 14, 16, 17, 18, 19, 20, 21};

// ---------------- scratch ----------------
__device__ float g_JT[NJ * 3];
__device__ float g_JS[NJ * 30];
__device__ __align__(16) float g_GT[NJ * 12 * N_BODY];      // [j*12+e][n]
__device__ __align__(16) float g_transT[3 * N_BODY];        // [c][n]
__device__ __align__(16) __nv_bfloat16 g_A[GM * GK];        // [n][k]
__device__ __align__(16) __nv_bfloat16 g_B[(size_t)GN * GK];// [c*NVP+v][k]
__device__ __align__(16) float g_jpart[(size_t)NVB * N_BODY * 72];

// ---------------- f32x2 helpers ----------------
__device__ __forceinline__ ull pk2(float a, float b) {
    ull r; asm("mov.b64 %0, {%1, %2};" : "=l"(r) : "f"(a), "f"(b)); return r;
}
__device__ __forceinline__ void upk2(float& a, float& b, ull v) {
    asm("mov.b64 {%0, %1}, %2;" : "=f"(a), "=f"(b) : "l"(v));
}
__device__ __forceinline__ ull fma2_(ull a, ull b, ull c) {
    ull d; asm("fma.rn.f32x2 %0, %1, %2, %3;" : "=l"(d) : "l"(a), "l"(b), "l"(c)); return d;
}

// ---------------- tensor-core helpers ----------------
__device__ __forceinline__ void cp16(unsigned dst, const void* src) {
    asm volatile("cp.async.cg.shared.global [%0], [%1], 16;" :: "r"(dst), "l"(src));
}
__device__ __forceinline__ void ldm4(unsigned* r, unsigned addr) {
    asm volatile("ldmatrix.sync.aligned.m8n8.x4.shared.b16 {%0,%1,%2,%3}, [%4];"
        : "=r"(r[0]), "=r"(r[1]), "=r"(r[2]), "=r"(r[3]) : "r"(addr));
}
__device__ __forceinline__ void mma16816(float* d, const unsigned* a, const unsigned* b) {
    asm volatile("mma.sync.aligned.m16n8k16.row.col.f32.bf16.bf16.f32 "
        "{%0,%1,%2,%3}, {%4,%5,%6,%7}, {%8,%9}, {%0,%1,%2,%3};"
        : "+f"(d[0]), "+f"(d[1]), "+f"(d[2]), "+f"(d[3])
        : "r"(a[0]), "r"(a[1]), "r"(a[2]), "r"(a[3]), "r"(b[0]), "r"(b[1]));
}
__device__ __forceinline__ int swz(int off) { return off ^ ((off >> 3) & 0x70); }

__device__ __forceinline__ unsigned bf2pack(float lo, float hi) {
    __nv_bfloat162 h = __floats2bfloat162_rn(lo, hi);
    return reinterpret_cast<unsigned&>(h);
}

// ---------------- merged prep kernel ----------------
// blocks [0,24): J_regressor reductions (k_pre)
// blocks [24, 24+GN/8): bf16 B build, vectorized 16B stores
__global__ void __launch_bounds__(256) k_prep(const float* __restrict__ Jreg,
                                              const float* __restrict__ vt,
                                              const float* __restrict__ sd,
                                              const float* __restrict__ pd) {
    if (blockIdx.x < 24) {
        int j = blockIdx.x;
        int tid = threadIdx.x;
        float acc[33];
#pragma unroll
        for (int i = 0; i < 33; i++) acc[i] = 0.f;
        for (int v = tid; v < NV; v += 256) {
            float r = Jreg[j * NV + v];
#pragma unroll
            for (int c = 0; c < 3; c++) acc[c] += r * vt[v * 3 + c];
#pragma unroll
            for (int i = 0; i < 30; i++) acc[3 + i] += r * sd[v * 30 + i];
        }
#pragma unroll
        for (int i = 0; i < 33; i++) {
#pragma unroll
            for (int off = 16; off > 0; off >>= 1)
                acc[i] += __shfl_down_sync(0xffffffff, acc[i], off);
        }
        __shared__ float red[8][34];
        int wid = tid >> 5, lane = tid & 31;
        if (lane == 0) {
#pragma unroll
            for (int i = 0; i < 33; i++) red[wid][i] = acc[i];
        }
        __syncthreads();
        if (tid < 33) {
            float s = 0.f;
#pragma unroll
            for (int wq = 0; wq < 8; wq++) s += red[wq][tid];
            if (tid < 3) g_JT[j * 3 + tid] = s;
            else         g_JS[j * 30 + (tid - 3)] = s;
        }
    } else {
        int wid = threadIdx.x >> 5, lane = threadIdx.x & 31;
        int row = (blockIdx.x - 24) * 8 + wid;
        int c = row / NVP, v = row % NVP;
        int k0 = lane * 8;
        float vals[8];
#pragma unroll
        for (int u = 0; u < 8; u++) {
            int k = k0 + u;
            float val = 0.f;
            if (v < NV) {
                if (k < 10)        val = sd[v * 30 + c * 10 + k];
                else if (k < 217)  val = pd[(size_t)v * 621 + c * 207 + (k - 10)];
                else if (k == 217) val = vt[v * 3 + c];
                else if (k == 218) {
                    float x = vt[v * 3 + c];
                    val = x - __bfloat162float(__float2bfloat16(x));
                }
            }
            vals[u] = val;
        }
        uint4 q;
        q.x = bf2pack(vals[0], vals[1]);
        q.y = bf2pack(vals[2], vals[3]);
        q.z = bf2pack(vals[4], vals[5]);
        q.w = bf2pack(vals[6], vals[7]);
        *(uint4*)(g_B + (size_t)row * GK + k0) = q;
    }
}

// ---------------- kernel: rodrigues + FK + A row (4 bodies/block) ----------------
__global__ void __launch_bounds__(128) k_body(const float* __restrict__ betas,
                                              const float* __restrict__ thetas,
                                              const float* __restrict__ trans) {
    int wb = threadIdx.x >> 5;
    int lane = threadIdx.x & 31;
    int n = blockIdx.x * 4 + wb;
    __shared__ float sR[4][NJ][9];
    __shared__ float sJ[4][NJ][3];
    __shared__ float sT[4][NJ][3];
    __shared__ float sG[4][NJ][12];

    if (lane < NJ) {
        int j = lane;
        float b[10];
#pragma unroll
        for (int k = 0; k < 10; k++) b[k] = betas[n * 10 + k];
#pragma unroll
        for (int c = 0; c < 3; c++) {
            float a = g_JT[j * 3 + c];
#pragma unroll
            for (int k = 0; k < 10; k++) a += g_JS[j * 30 + c * 10 + k] * b[k];
            sJ[wb][j][c] = a;
        }
        float rx = thetas[n * 72 + j * 3 + 0];
        float ry = thetas[n * 72 + j * 3 + 1];
        float rz = thetas[n * 72 + j * 3 + 2];
        float th = sqrtf(rx * rx + ry * ry + rz * rz) + 1e-8f;
        float inv = 1.0f / th;
        float x = rx * inv, y = ry * inv, z = rz * inv;
        float ct = cosf(th), st = sinf(th), oc = 1.0f - ct;
        sR[wb][j][0] = ct + oc * x * x;      sR[wb][j][1] = oc * x * y - st * z;  sR[wb][j][2] = oc * x * z + st * y;
        sR[wb][j][3] = oc * y * x + st * z;  sR[wb][j][4] = ct + oc * y * y;      sR[wb][j][5] = oc * y * z - st * x;
        sR[wb][j][6] = oc * z * x - st * y;  sR[wb][j][7] = oc * z * y + st * x;  sR[wb][j][8] = ct + oc * z * z;
    }
    __syncwarp();
    if (lane < NJ) {
        int j = lane;
        if (j == 0) {
#pragma unroll
            for (int c = 0; c < 3; c++) sT[wb][0][c] = sJ[wb][0][c];
        } else {
            int p = d_parents[j];
#pragma unroll
            for (int c = 0; c < 3; c++) sT[wb][j][c] = sJ[wb][j][c] - sJ[wb][p][c];
        }
    }
    __syncwarp();
    if (lane == 0) {
#pragma unroll
        for (int r = 0; r < 3; r++) {
            sG[wb][0][r * 4 + 0] = sR[wb][0][r * 3 + 0];
            sG[wb][0][r * 4 + 1] = sR[wb][0][r * 3 + 1];
            sG[wb][0][r * 4 + 2] = sR[wb][0][r * 3 + 2];
            sG[wb][0][r * 4 + 3] = sT[wb][0][r];
        }
        for (int j = 1; j < NJ; j++) {
            int p = d_parents[j];
            float Rn[9], tn[3];
#pragma unroll
            for (int r = 0; r < 3; r++) {
#pragma unroll
                for (int c = 0; c < 3; c++) {
                    Rn[r * 3 + c] = sG[wb][p][r * 4 + 0] * sR[wb][j][0 * 3 + c]
                                  + sG[wb][p][r * 4 + 1] * sR[wb][j][1 * 3 + c]
                                  + sG[wb][p][r * 4 + 2] * sR[wb][j][2 * 3 + c];
                }
                tn[r] = sG[wb][p][r * 4 + 3]
                      + sG[wb][p][r * 4 + 0] * sT[wb][j][0]
                      + sG[wb][p][r * 4 + 1] * sT[wb][j][1]
                      + sG[wb][p][r * 4 + 2] * sT[wb][j][2];
            }
#pragma unroll
            for (int r = 0; r < 3; r++) {
                sG[wb][j][r * 4 + 0] = Rn[r * 3 + 0];
                sG[wb][j][r * 4 + 1] = Rn[r * 3 + 1];
                sG[wb][j][r * 4 + 2] = Rn[r * 3 + 2];
                sG[wb][j][r * 4 + 3] = tn[r];
            }
        }
    }
    __syncwarp();
    if (lane < NJ) {
        int j = lane;
        float t0 = sG[wb][j][3]  - (sG[wb][j][0] * sJ[wb][j][0] + sG[wb][j][1] * sJ[wb][j][1] + sG[wb][j][2]  * sJ[wb][j][2]);
        float t1 = sG[wb][j][7]  - (sG[wb][j][4] * sJ[wb][j][0] + sG[wb][j][5] * sJ[wb][j][1] + sG[wb][j][6]  * sJ[wb][j][2]);
        float t2 = sG[wb][j][11] - (sG[wb][j][8] * sJ[wb][j][0] + sG[wb][j][9] * sJ[wb][j][1] + sG[wb][j][10] * sJ[wb][j][2]);
        sG[wb][j][3] = t0; sG[wb][j][7] = t1; sG[wb][j][11] = t2;
    }
    __syncwarp();
    for (int idx = lane; idx < NJ * 12; idx += 32)
        g_GT[idx * N_BODY + n] = sG[wb][idx / 12][idx % 12];
#pragma unroll
    for (int t = 0; t < 8; t++) {
        int k = t * 32 + lane;
        float val = 0.f;
        if (k < 10) val = betas[n * 10 + k];
        else if (k < 217) {
            int idx = k - 10;
            int j = idx / 9 + 1, e = idx % 9;
            val = sR[wb][j][e];
            if (e == 0 || e == 4 || e == 8) val -= 1.0f;
        }
        else if (k == 217 || k == 218) val = 1.0f;
        g_A[n * GK + k] = __float2bfloat16(val);
    }
    if (lane < 3) g_transT[lane * N_BODY + n] = trans[n * 3 + lane];
}

// ---------------- fused kernel: GEMM + LBS + joint partials ----------------
// block: 64 bodies x 64 verts, 256 threads, 8 warps (2M x 4N), warp tile 32x16 per c
// smem (floats):
//   stages: A 2x8KB @0B, B 2x24KB @16384B  -> GEMM phase only
//   Ct[64][196]   @0      (12544 fl) — overlays stages after mainloop
//   jreg_s[24][65] @12544 (1560 fl)
//   w_s[24][128]  @14104  (3072 fl)  (pair-duplicated)
//   sG[24][16][24] @17176 (9216 fl)  — [j][bp][e-pair] per 32-body half
#define CTS 196
#define JREG_F 12544
#define W_F    14104
#define SG_F   17176
#define SMEMB  105568

__global__ void __launch_bounds__(256, 2) k_fused(const float* __restrict__ w,
                                                  const float* __restrict__ jreg,
                                                  float* __restrict__ out) {
    extern __shared__ float sm[];
    unsigned smem = (unsigned)__cvta_generic_to_shared((char*)sm);
    float* Ct     = sm;
    float* jreg_s = sm + JREG_F;
    float* w_s    = sm + W_F;
    float* sG     = sm + SG_F;

    int tid = threadIdx.x, lane = tid & 31, wid = tid >> 5;
    int warp_m = (wid >> 2) * 32, warp_n = (wid & 3) * 16;
    int vbIdx = blockIdx.x;
    int vb = vbIdx * 64;
    int mb = blockIdx.y * 64;

    float acc[3][2][2][4];
#pragma unroll
    for (int c = 0; c < 3; c++)
#pragma unroll
        for (int mf = 0; mf < 2; mf++)
#pragma unroll
            for (int nf = 0; nf < 2; nf++)
#pragma unroll
                for (int q = 0; q < 4; q++) acc[c][mf][nf][q] = 0.f;

#define LDSTG(st, kb)                                                              \
    {                                                                              \
        unsigned sa = smem + (st) * 8192;                                          \
        _Pragma("unroll")                                                          \
        for (int t = 0; t < 2; t++) {                                              \
            int i = tid + t * 256; int r = i >> 3, u = i & 7;                      \
            cp16(sa + swz(r * 128 + u * 16),                                       \
                 (const char*)g_A + (size_t)(mb + r) * 512 + (kb) * 128 + u * 16); \
        }                                                                          \
        _Pragma("unroll")                                                          \
        for (int t = 0; t < 6; t++) {                                              \
            int i = tid + t * 256; int c = i >> 9, rr = (i >> 3) & 63, u = i & 7;  \
            unsigned sb = smem + 16384 + (st) * 24576 + c * 8192;                  \
            cp16(sb + swz(rr * 128 + u * 16),                                      \
                 (const char*)g_B + (size_t)(c * NVP + vb + rr) * 512 + (kb) * 128 + u * 16); \
        }                                                                          \
        asm volatile("cp.async.commit_group;");                                    \
    }

    LDSTG(0, 0);
#pragma unroll
    for (int kb = 0; kb < 4; kb++) {
        if (kb < 3) LDSTG((kb + 1) & 1, kb + 1);
        if (kb < 3) asm volatile("cp.async.wait_group 1;");
        else        asm volatile("cp.async.wait_group 0;");
        __syncthreads();
        unsigned sa = smem + (kb & 1) * 8192;
#pragma unroll
        for (int s = 0; s < 4; s++) {
            unsigned af[2][4];
#pragma unroll
            for (int mf = 0; mf < 2; mf++) {
                int row = warp_m + mf * 16 + (lane & 7) + ((lane >> 3) & 1) * 8;
                ldm4(af[mf], sa + swz(row * 128 + s * 32 + ((lane >> 4) & 1) * 16));
            }
#pragma unroll
            for (int c = 0; c < 3; c++) {
                unsigned sb = smem + 16384 + (kb & 1) * 24576 + c * 8192;
                unsigned r[4];
                int row = warp_n + (lane & 7) + ((lane >> 4) & 1) * 8;
                ldm4(r, sb + swz(row * 128 + s * 32 + ((lane >> 3) & 1) * 16));
#pragma unroll
                for (int mf = 0; mf < 2; mf++) {
                    mma16816(acc[c][mf][0], af[mf], r);
                    mma16816(acc[c][mf][1], af[mf], r + 2);
                }
            }
        }
        __syncthreads();
    }
#undef LDSTG

    // ---- epilogue: acc -> Ct (v_posed; vt folded via hi/lo columns) ----
#pragma unroll
    for (int c = 0; c < 3; c++)
#pragma unroll
        for (int mf = 0; mf < 2; mf++)
#pragma unroll
            for (int nf = 0; nf < 2; nf++) {
                int r0 = warp_m + mf * 16 + (lane >> 2);
                int L = warp_n + nf * 8 + (lane & 3) * 2;
                Ct[r0 * CTS + L * 3 + c]             = acc[c][mf][nf][0];
                Ct[r0 * CTS + (L + 1) * 3 + c]       = acc[c][mf][nf][1];
                Ct[(r0 + 8) * CTS + L * 3 + c]       = acc[c][mf][nf][2];
                Ct[(r0 + 8) * CTS + (L + 1) * 3 + c] = acc[c][mf][nf][3];
            }

    // ---- load w (pair-duplicated) + jreg (row-padded 65); shift-only indexing ----
    {
        int vl = tid >> 2, sub = tid & 3;
#pragma unroll
        for (int t = 0; t < 6; t++) {
            int j = sub + t * 4;
            int v = vb + vl;
            float wv = (v < NV) ? w[v * 24 + j] : 0.f;
            w_s[j * 128 + vl * 2]     = wv;
            w_s[j * 128 + vl * 2 + 1] = wv;
            jreg_s[j * 65 + vl] = (v < NV) ? jreg[v * 24 + j] : 0.f;
        }
    }

    // ---- skinning in place, two 32-body halves; thread = body-pair(16) x vert-quad(16) ----
    int bp = tid >> 4, vq = tid & 15;
#pragma unroll 1
    for (int h = 0; h < 2; h++) {
        __syncthreads();   // epilogue/w/jreg stores done (h=0); prior-half sG reads done (h=1)
        // sG layout: [j][bp][e][pair]: 24 contiguous floats per (j,bp)
        for (int i = tid; i < 288 * 32; i += 256) {
            int rest = i >> 5, b2 = i & 31;
            int j = rest / 12, e = rest - j * 12;
            sG[j * 384 + (b2 >> 1) * 24 + e * 2 + (b2 & 1)] =
                g_GT[rest * N_BODY + mb + h * 32 + b2];
        }
        __syncthreads();

        int n0 = h * 32 + bp * 2;
        ull B[4][3], o[4][3];
#pragma unroll
        for (int vv = 0; vv < 4; vv++)
#pragma unroll
            for (int c = 0; c < 3; c++)
                B[vv][c] = pk2(Ct[n0 * CTS + (vq * 4 + vv) * 3 + c],
                               Ct[(n0 + 1) * CTS + (vq * 4 + vv) * 3 + c]);
#pragma unroll
        for (int c = 0; c < 3; c++) {
            ull t2 = *(const ull*)(g_transT + c * N_BODY + mb + n0);
#pragma unroll
            for (int vv = 0; vv < 4; vv++) o[vv][c] = t2;
        }
#pragma unroll 1
        for (int j = 0; j < NJ; j++) {
            const ulonglong2* gj = (const ulonglong2*)(sG + j * 384 + bp * 24);
            ulonglong2 q0 = gj[0], q1 = gj[1], q2 = gj[2], q3 = gj[3], q4 = gj[4], q5 = gj[5];
            const ulonglong2* wj = (const ulonglong2*)(w_s + j * 128 + vq * 8);
            ulonglong2 wA = wj[0], wB = wj[1];
            ull g2[12] = {q0.x, q0.y, q1.x, q1.y, q2.x, q2.y,
                          q3.x, q3.y, q4.x, q4.y, q5.x, q5.y};
            ull w2v[4] = {wA.x, wA.y, wB.x, wB.y};
#pragma unroll
            for (int vv = 0; vv < 4; vv++) {
                ull tx = fma2_(g2[0], B[vv][0], fma2_(g2[1], B[vv][1], fma2_(g2[2],  B[vv][2], g2[3])));
                ull ty = fma2_(g2[4], B[vv][0], fma2_(g2[5], B[vv][1], fma2_(g2[6],  B[vv][2], g2[7])));
                ull tz = fma2_(g2[8], B[vv][0], fma2_(g2[9], B[vv][1], fma2_(g2[10], B[vv][2], g2[11])));
                o[vv][0] = fma2_(w2v[vv], tx, o[vv][0]);
                o[vv][1] = fma2_(w2v[vv], ty, o[vv][1]);
                o[vv][2] = fma2_(w2v[vv], tz, o[vv][2]);
            }
        }
        // write back: each thread owns rows n0,n0+1 / cols vq*4..+3 — no hazard
#pragma unroll
        for (int vv = 0; vv < 4; vv++)
#pragma unroll
            for (int c = 0; c < 3; c++) {
                float x0, x1;
                upk2(x0, x1, o[vv][c]);
                Ct[n0 * CTS + (vq * 4 + vv) * 3 + c]       = x0;
                Ct[(n0 + 1) * CTS + (vq * 4 + vv) * 3 + c] = x1;
            }
    }
    __syncthreads();

    // ---- stream out (float2, 256B-contiguous per warp, shift-only indexing) ----
    int nvleft = NV - vb; if (nvleft > 64) nvleft = 64;
    int flim2 = nvleft * 3 / 2;
#pragma unroll 1
    for (int t = 0; t < 8; t++) {
        int nl = wid + t * 8;
        const float* src = Ct + nl * CTS;
        float* dst = out + (size_t)(mb + nl) * (NV * 3) + (size_t)vb * 3;
#pragma unroll
        for (int s = 0; s < 3; s++) {
            int q = lane + s * 32;
            if (q < flim2)
                *(float2*)(dst + 2 * q) = *(const float2*)(src + 2 * q);
        }
    }

    // ---- joint partials: thread = body (64) x joint-sextet (4) ----
    {
        int nl = tid >> 2, jq = tid & 3;
        float ja[18];
#pragma unroll
        for (int q = 0; q < 18; q++) ja[q] = 0.f;
#pragma unroll 4
        for (int v = 0; v < 64; v++) {
            float r0 = Ct[nl * CTS + v * 3 + 0];
            float r1 = Ct[nl * CTS + v * 3 + 1];
            float r2 = Ct[nl * CTS + v * 3 + 2];
#pragma unroll
            for (int j = 0; j < 6; j++) {
                float jr = jreg_s[(jq * 6 + j) * 65 + v];
                ja[j * 3 + 0] += jr * r0;
                ja[j * 3 + 1] += jr * r1;
                ja[j * 3 + 2] += jr * r2;
            }
        }
        float* dst = g_jpart + (size_t)vbIdx * (N_BODY * 72) + (mb + nl) * 72 + jq * 18;
#pragma unroll
        for (int q = 0; q < 18; q++) dst[q] = ja[q];
    }
}

// ---------------- kernel: reduce joint partials (float4) ----------------
__global__ void __launch_bounds__(256) k_jred(float* __restrict__ jout) {
    int i = (blockIdx.x * 256 + threadIdx.x) * 4;
    if (i < N_BODY * 72) {
        float4 s = make_float4(0.f, 0.f, 0.f, 0.f);
        for (int b = 0; b < NVB; b++) {
            float4 q = *(const float4*)(g_jpart + (size_t)b * (N_BODY * 72) + i);
            s.x += q.x; s.y += q.y; s.z += q.z; s.w += q.w;
        }
        *(float4*)(jout + i) = s;
    }
}

// ---------------- launch ----------------
extern "C" void kernel_launch(void* const* d_in, const int* in_sizes, int n_in,
                              void* d_out, int out_size) {
    const float* betas  = (const float*)d_in[0];
    const float* thetas = (const float*)d_in[1];
    const float* trans  = (const float*)d_in[2];
    const float* vt     = (const float*)d_in[3];
    const float* sd     = (const float*)d_in[4];
    const float* pd     = (const float*)d_in[5];
    const float* Jreg   = (const float*)d_in[6];
    const float* jreg   = (const float*)d_in[7];
    const float* w      = (const float*)d_in[8];
    float* out  = (float*)d_out;
    float* jout = out + (size_t)N_BODY * NV * 3;

    k_prep<<<24 + GN / 8, 256>>>(Jreg, vt, sd, pd);
    k_body<<<N_BODY / 4, 128>>>(betas, thetas, trans);

    cudaFuncSetAttribute(k_fused, cudaFuncAttributeMaxDynamicSharedMemorySize, SMEMB);
    dim3 fgrid(NVB, N_BODY / 64);
    k_fused<<<fgrid, 256, SMEMB>>>(w, jreg, out);

    k_jred<<<(N_BODY * 72 + 1023) / 1024, 256>>>(jout);
}